// round 3
// baseline (speedup 1.0000x reference)
#include <cuda_runtime.h>
#include <math.h>

// Problem constants
#define B_  2
#define S_  2048
#define D_  768
#define H_  12
#define HD_ 64
#define M_  (B_*S_)   // 4096

// ---------------------------------------------------------------------------
// Device scratch (allocation-free rule: static __device__ arrays)
// ---------------------------------------------------------------------------
__device__ float g_q[B_*H_*S_*HD_];    // [b,h,s,hd]
__device__ float g_k[B_*H_*S_*HD_];
__device__ float g_v[B_*H_*S_*HD_];
__device__ float g_ctx[M_*D_];         // [b,s,d]

// ---------------------------------------------------------------------------
// SGEMM: C[128x128] tile, BK=16, 256 threads, 8x8 per-thread register tile
// A: [M,768] row-major, W: [768,768] row-major
// ---------------------------------------------------------------------------
#define BM 128
#define BN 128
#define BKK 16

__device__ __forceinline__ void sgemm_tile_768(
    const float* __restrict__ A, const float* __restrict__ W,
    int rowBase, int colBase, float acc[8][8])
{
    __shared__ float As[BKK][BM];   // k-major (transposed A tile)
    __shared__ float Bs[BKK][BN];

    const int tid = threadIdx.x;
    const int tr  = tid >> 4;       // 0..15
    const int tc  = tid & 15;       // 0..15

    // A loader: 128x16 = 512 float4, 2 per thread
    const int ar  = tid >> 2;              // 0..63
    const int as4 = (tid & 3) << 2;        // 0,4,8,12
    // W loader: 16x128 = 512 float4, 2 per thread
    const int br  = tid >> 5;              // 0..7
    const int bc4 = (tid & 31) << 2;       // 0..124

    const float* Ap0 = A + (size_t)(rowBase + ar) * D_ + as4;
    const float* Ap1 = Ap0 + (size_t)64 * D_;
    const float* Wp0 = W + (size_t)br * D_ + colBase + bc4;
    const float* Wp1 = Wp0 + (size_t)8 * D_;

    for (int k0 = 0; k0 < D_; k0 += BKK) {
        float4 a0 = *(const float4*)(Ap0 + k0);
        float4 a1 = *(const float4*)(Ap1 + k0);
        float4 b0 = *(const float4*)(Wp0 + (size_t)k0 * D_);
        float4 b1 = *(const float4*)(Wp1 + (size_t)k0 * D_);
        __syncthreads();   // previous iteration's reads complete
        As[as4+0][ar]    = a0.x; As[as4+1][ar]    = a0.y;
        As[as4+2][ar]    = a0.z; As[as4+3][ar]    = a0.w;
        As[as4+0][ar+64] = a1.x; As[as4+1][ar+64] = a1.y;
        As[as4+2][ar+64] = a1.z; As[as4+3][ar+64] = a1.w;
        *(float4*)&Bs[br][bc4]   = b0;
        *(float4*)&Bs[br+8][bc4] = b1;
        __syncthreads();
        #pragma unroll
        for (int k = 0; k < BKK; k++) {
            float af[8], bf[8];
            *(float4*)&af[0] = *(const float4*)&As[k][tr << 3];
            *(float4*)&af[4] = *(const float4*)&As[k][(tr << 3) + 4];
            *(float4*)&bf[0] = *(const float4*)&Bs[k][tc << 3];
            *(float4*)&bf[4] = *(const float4*)&Bs[k][(tc << 3) + 4];
            #pragma unroll
            for (int i = 0; i < 8; i++)
                #pragma unroll
                for (int j = 0; j < 8; j++)
                    acc[i][j] = fmaf(af[i], bf[j], acc[i][j]);
        }
    }
}

// ---------------------------------------------------------------------------
// QKV projection: y = x @ W + b, written in head layout [b,h,s,hd]
// grid (6, 32, 3) — z selects Q/K/V
// ---------------------------------------------------------------------------
__global__ void __launch_bounds__(256)
qkv_gemm_kernel(const float* __restrict__ x,
                const float* __restrict__ Wq, const float* __restrict__ bq,
                const float* __restrict__ Wk, const float* __restrict__ bk,
                const float* __restrict__ Wv, const float* __restrict__ bv)
{
    const float* W; const float* bias; float* Cout;
    if (blockIdx.z == 0)      { W = Wq; bias = bq; Cout = g_q; }
    else if (blockIdx.z == 1) { W = Wk; bias = bk; Cout = g_k; }
    else                      { W = Wv; bias = bv; Cout = g_v; }

    const int rowBase = blockIdx.y * BM;
    const int colBase = blockIdx.x * BN;
    float acc[8][8] = {};
    sgemm_tile_768(x, W, rowBase, colBase, acc);

    const int tr = threadIdx.x >> 4;
    const int tc = threadIdx.x & 15;
    #pragma unroll
    for (int i = 0; i < 8; i++) {
        int row = rowBase + (tr << 3) + i;
        int b   = row >> 11;          // / S_
        int s   = row & (S_ - 1);
        #pragma unroll
        for (int j = 0; j < 8; j += 4) {
            int col = colBase + (tc << 3) + j;
            int h   = col >> 6;
            int hd  = col & 63;
            float4 r;
            r.x = acc[i][j+0] + bias[col+0];
            r.y = acc[i][j+1] + bias[col+1];
            r.z = acc[i][j+2] + bias[col+2];
            r.w = acc[i][j+3] + bias[col+3];
            *(float4*)&Cout[(((size_t)(b * H_ + h)) * S_ + s) * HD_ + hd] = r;
        }
    }
}

// ---------------------------------------------------------------------------
// Output projection: out = ctx @ Wo + bo, plain [b,s,d]
// ---------------------------------------------------------------------------
__global__ void __launch_bounds__(256)
out_gemm_kernel(const float* __restrict__ Wo, const float* __restrict__ bo,
                float* __restrict__ out)
{
    const int rowBase = blockIdx.y * BM;
    const int colBase = blockIdx.x * BN;
    float acc[8][8] = {};
    sgemm_tile_768(g_ctx, Wo, rowBase, colBase, acc);

    const int tr = threadIdx.x >> 4;
    const int tc = threadIdx.x & 15;
    #pragma unroll
    for (int i = 0; i < 8; i++) {
        int row = rowBase + (tr << 3) + i;
        #pragma unroll
        for (int j = 0; j < 8; j += 4) {
            int col = colBase + (tc << 3) + j;
            float4 r;
            r.x = acc[i][j+0] + bo[col+0];
            r.y = acc[i][j+1] + bo[col+1];
            r.z = acc[i][j+2] + bo[col+2];
            r.w = acc[i][j+3] + bo[col+3];
            *(float4*)&out[(size_t)row * D_ + col] = r;
        }
    }
}

// ---------------------------------------------------------------------------
// Flash attention: 64 q-rows per block, 64-key tiles, online softmax.
// grid (S/64=32, B*H=24), 256 threads (16x16), each owns 4x4 of the 64x64 tile.
// Smem (dynamic, 68608 B): Qs/Ks/Ps transposed with pad 68 for conflict-free
// float4 fragment reads; Vs natural layout stride 64.
// ---------------------------------------------------------------------------
#define QP 68
#define AT_SMEM ((3 * 64 * QP + 64 * 64) * 4)

__global__ void __launch_bounds__(256) attn_kernel()
{
    extern __shared__ float sm[];
    float* Qs = sm;                  // [64(kk)][68(qrow)]
    float* Ks = sm + 64 * QP;        // [64(kk)][68(krow)]
    float* Ps = sm + 2 * 64 * QP;    // [64(kv)][68(qrow)]
    float* Vs = sm + 3 * 64 * QP;    // [64(kv)][64(hd)]

    const int tid = threadIdx.x;
    const int ty  = tid >> 4;        // 0..15
    const int tx  = tid & 15;        // 0..15
    const int ty4 = ty << 2;
    const int tx4 = tx << 2;
    const int bh  = blockIdx.y;
    const int q0  = blockIdx.x << 6;

    const float* Qb = g_q + (size_t)bh * S_ * HD_;
    const float* Kb = g_k + (size_t)bh * S_ * HD_;
    const float* Vb = g_v + (size_t)bh * S_ * HD_;

    const int lr  = tid >> 4;            // loader row 0..15
    const int lc4 = (tid & 15) << 2;     // loader col*4

    // Load Q tile transposed: Qs[kk][qrow]
    #pragma unroll
    for (int rr = lr; rr < 64; rr += 16) {
        float4 v = *(const float4*)(Qb + (size_t)(q0 + rr) * HD_ + lc4);
        Qs[(lc4+0)*QP + rr] = v.x;
        Qs[(lc4+1)*QP + rr] = v.y;
        Qs[(lc4+2)*QP + rr] = v.z;
        Qs[(lc4+3)*QP + rr] = v.w;
    }

    float m_r[4] = {-1e30f, -1e30f, -1e30f, -1e30f};
    float l_r[4] = {0.f, 0.f, 0.f, 0.f};
    float o[4][4] = {};

    for (int kt = 0; kt < S_; kt += 64) {
        __syncthreads();  // previous PV reads (Ps,Vs) + Q stores visible
        #pragma unroll
        for (int rr = lr; rr < 64; rr += 16) {
            float4 kv = *(const float4*)(Kb + (size_t)(kt + rr) * HD_ + lc4);
            Ks[(lc4+0)*QP + rr] = kv.x;
            Ks[(lc4+1)*QP + rr] = kv.y;
            Ks[(lc4+2)*QP + rr] = kv.z;
            Ks[(lc4+3)*QP + rr] = kv.w;
            float4 vv = *(const float4*)(Vb + (size_t)(kt + rr) * HD_ + lc4);
            *(float4*)&Vs[rr * 64 + lc4] = vv;
        }
        __syncthreads();

        // S = Q @ K^T  (4x4 per thread)
        float sv[4][4] = {};
        {
            const float* qp = Qs + ty4;
            const float* kp = Ks + tx4;
            #pragma unroll 8
            for (int kk = 0; kk < 64; kk++) {
                float4 qf = *(const float4*)qp;
                float4 kf = *(const float4*)kp;
                float qa[4] = {qf.x, qf.y, qf.z, qf.w};
                float ka[4] = {kf.x, kf.y, kf.z, kf.w};
                #pragma unroll
                for (int i = 0; i < 4; i++)
                    #pragma unroll
                    for (int j = 0; j < 4; j++)
                        sv[i][j] = fmaf(qa[i], ka[j], sv[i][j]);
                qp += QP; kp += QP;
            }
        }

        // Online softmax: row reduce across the 16-lane tx group via shfl
        #pragma unroll
        for (int i = 0; i < 4; i++) {
            #pragma unroll
            for (int j = 0; j < 4; j++) sv[i][j] *= 0.125f;  // 1/sqrt(64)
            float mx = fmaxf(fmaxf(sv[i][0], sv[i][1]), fmaxf(sv[i][2], sv[i][3]));
            mx = fmaxf(mx, __shfl_xor_sync(0xffffffffu, mx, 1));
            mx = fmaxf(mx, __shfl_xor_sync(0xffffffffu, mx, 2));
            mx = fmaxf(mx, __shfl_xor_sync(0xffffffffu, mx, 4));
            mx = fmaxf(mx, __shfl_xor_sync(0xffffffffu, mx, 8));
            float mnew  = fmaxf(m_r[i], mx);
            float alpha = __expf(m_r[i] - mnew);
            m_r[i] = mnew;
            float rs = 0.f;
            #pragma unroll
            for (int j = 0; j < 4; j++) {
                float p = __expf(sv[i][j] - mnew);
                sv[i][j] = p;
                rs += p;
            }
            rs += __shfl_xor_sync(0xffffffffu, rs, 1);
            rs += __shfl_xor_sync(0xffffffffu, rs, 2);
            rs += __shfl_xor_sync(0xffffffffu, rs, 4);
            rs += __shfl_xor_sync(0xffffffffu, rs, 8);
            l_r[i] = l_r[i] * alpha + rs;
            #pragma unroll
            for (int j = 0; j < 4; j++) o[i][j] *= alpha;
        }

        // Stage P transposed: Ps[kv][qrow]
        #pragma unroll
        for (int i = 0; i < 4; i++)
            #pragma unroll
            for (int j = 0; j < 4; j++)
                Ps[(tx4 + j) * QP + ty4 + i] = sv[i][j];
        __syncthreads();

        // O += P @ V
        {
            const float* pp = Ps + ty4;
            const float* vp = Vs + tx4;
            #pragma unroll 8
            for (int kv = 0; kv < 64; kv++) {
                float4 pf = *(const float4*)pp;
                float4 vf = *(const float4*)vp;
                float pa[4] = {pf.x, pf.y, pf.z, pf.w};
                float va[4] = {vf.x, vf.y, vf.z, vf.w};
                #pragma unroll
                for (int i = 0; i < 4; i++)
                    #pragma unroll
                    for (int j = 0; j < 4; j++)
                        o[i][j] = fmaf(pa[i], va[j], o[i][j]);
                pp += QP; vp += 64;
            }
        }
    }

    // Epilogue: normalize and write ctx in [b,s,d] layout
    const int b = bh / H_;
    const int h = bh - b * H_;
    #pragma unroll
    for (int i = 0; i < 4; i++) {
        float inv = 1.0f / l_r[i];
        int sg = q0 + ty4 + i;
        float4 r;
        r.x = o[i][0] * inv;
        r.y = o[i][1] * inv;
        r.z = o[i][2] * inv;
        r.w = o[i][3] * inv;
        *(float4*)&g_ctx[((size_t)(b * S_ + sg)) * D_ + h * HD_ + tx4] = r;
    }
}

// ---------------------------------------------------------------------------
// Launch
// ---------------------------------------------------------------------------
extern "C" void kernel_launch(void* const* d_in, const int* in_sizes, int n_in,
                              void* d_out, int out_size)
{
    (void)in_sizes; (void)n_in; (void)out_size;
    const float* x  = (const float*)d_in[0];
    const float* Wq = (const float*)d_in[1];
    const float* bq = (const float*)d_in[2];
    const float* Wk = (const float*)d_in[3];
    const float* bk = (const float*)d_in[4];
    const float* Wv = (const float*)d_in[5];
    const float* bv = (const float*)d_in[6];
    const float* Wo = (const float*)d_in[7];
    const float* bo = (const float*)d_in[8];
    float* out = (float*)d_out;

    cudaFuncSetAttribute(attn_kernel,
                         cudaFuncAttributeMaxDynamicSharedMemorySize, AT_SMEM);

    qkv_gemm_kernel<<<dim3(D_/BN, M_/BM, 3), 256>>>(x, Wq, bq, Wk, bk, Wv, bv);
    attn_kernel<<<dim3(S_/64, B_*H_), 256, AT_SMEM>>>();
    out_gemm_kernel<<<dim3(D_/BN, M_/BM), 256>>>(Wo, bo, out);
}

// round 5
// speedup vs baseline: 1.7683x; 1.7683x over previous
#include <cuda_runtime.h>
#include <math.h>
#include <stdint.h>

// Problem constants
#define B_  2
#define S_  2048
#define D_  768
#define H_  12
#define HD_ 64
#define M_  (B_*S_)   // 4096

// ---------------------------------------------------------------------------
// Device scratch (allocation-free rule: static __device__ arrays)
// ---------------------------------------------------------------------------
__device__ float g_q[B_*H_*S_*HD_];    // [b,h,s,hd]
__device__ float g_k[B_*H_*S_*HD_];
__device__ float g_v[B_*H_*S_*HD_];
__device__ float g_ctx[M_*D_];         // [b,s,d]

// ---------------------------------------------------------------------------
// Helpers: tf32 rounding + mma.sync
// ---------------------------------------------------------------------------
__device__ __forceinline__ uint32_t tf32r(float x) {
    uint32_t u;
    asm("cvt.rna.tf32.f32 %0, %1;" : "=r"(u) : "f"(x));
    return u;
}

__device__ __forceinline__ void mma_tf32(float c[4], const uint32_t a[4],
                                         uint32_t b0, uint32_t b1) {
    asm volatile(
        "mma.sync.aligned.m16n8k8.row.col.f32.tf32.tf32.f32 "
        "{%0,%1,%2,%3},{%4,%5,%6,%7},{%8,%9},{%0,%1,%2,%3};"
        : "+f"(c[0]), "+f"(c[1]), "+f"(c[2]), "+f"(c[3])
        : "r"(a[0]), "r"(a[1]), "r"(a[2]), "r"(a[3]), "r"(b0), "r"(b1));
}

// ---------------------------------------------------------------------------
// SGEMM: C[128x128] tile, BK=16, 256 threads, 8x8 per-thread register tile
// (unchanged from R2 — FFMA, keeps full fp32 precision on projections)
// ---------------------------------------------------------------------------
#define BM 128
#define BN 128
#define BKK 16

__device__ __forceinline__ void sgemm_tile_768(
    const float* __restrict__ A, const float* __restrict__ W,
    int rowBase, int colBase, float acc[8][8])
{
    __shared__ float As[BKK][BM];   // k-major (transposed A tile)
    __shared__ float Bs[BKK][BN];

    const int tid = threadIdx.x;
    const int tr  = tid >> 4;       // 0..15
    const int tc  = tid & 15;       // 0..15

    const int ar  = tid >> 2;              // 0..63
    const int as4 = (tid & 3) << 2;        // 0,4,8,12
    const int br  = tid >> 5;              // 0..7
    const int bc4 = (tid & 31) << 2;       // 0..124

    const float* Ap0 = A + (size_t)(rowBase + ar) * D_ + as4;
    const float* Ap1 = Ap0 + (size_t)64 * D_;
    const float* Wp0 = W + (size_t)br * D_ + colBase + bc4;
    const float* Wp1 = Wp0 + (size_t)8 * D_;

    for (int k0 = 0; k0 < D_; k0 += BKK) {
        float4 a0 = *(const float4*)(Ap0 + k0);
        float4 a1 = *(const float4*)(Ap1 + k0);
        float4 b0 = *(const float4*)(Wp0 + (size_t)k0 * D_);
        float4 b1 = *(const float4*)(Wp1 + (size_t)k0 * D_);
        __syncthreads();
        As[as4+0][ar]    = a0.x; As[as4+1][ar]    = a0.y;
        As[as4+2][ar]    = a0.z; As[as4+3][ar]    = a0.w;
        As[as4+0][ar+64] = a1.x; As[as4+1][ar+64] = a1.y;
        As[as4+2][ar+64] = a1.z; As[as4+3][ar+64] = a1.w;
        *(float4*)&Bs[br][bc4]   = b0;
        *(float4*)&Bs[br+8][bc4] = b1;
        __syncthreads();
        #pragma unroll
        for (int k = 0; k < BKK; k++) {
            float af[8], bf[8];
            *(float4*)&af[0] = *(const float4*)&As[k][tr << 3];
            *(float4*)&af[4] = *(const float4*)&As[k][(tr << 3) + 4];
            *(float4*)&bf[0] = *(const float4*)&Bs[k][tc << 3];
            *(float4*)&bf[4] = *(const float4*)&Bs[k][(tc << 3) + 4];
            #pragma unroll
            for (int i = 0; i < 8; i++)
                #pragma unroll
                for (int j = 0; j < 8; j++)
                    acc[i][j] = fmaf(af[i], bf[j], acc[i][j]);
        }
    }
}

__global__ void __launch_bounds__(256)
qkv_gemm_kernel(const float* __restrict__ x,
                const float* __restrict__ Wq, const float* __restrict__ bq,
                const float* __restrict__ Wk, const float* __restrict__ bk,
                const float* __restrict__ Wv, const float* __restrict__ bv)
{
    const float* W; const float* bias; float* Cout;
    if (blockIdx.z == 0)      { W = Wq; bias = bq; Cout = g_q; }
    else if (blockIdx.z == 1) { W = Wk; bias = bk; Cout = g_k; }
    else                      { W = Wv; bias = bv; Cout = g_v; }

    const int rowBase = blockIdx.y * BM;
    const int colBase = blockIdx.x * BN;
    float acc[8][8] = {};
    sgemm_tile_768(x, W, rowBase, colBase, acc);

    const int tr = threadIdx.x >> 4;
    const int tc = threadIdx.x & 15;
    #pragma unroll
    for (int i = 0; i < 8; i++) {
        int row = rowBase + (tr << 3) + i;
        int b   = row >> 11;
        int s   = row & (S_ - 1);
        #pragma unroll
        for (int j = 0; j < 8; j += 4) {
            int col = colBase + (tc << 3) + j;
            int h   = col >> 6;
            int hd  = col & 63;
            float4 r;
            r.x = acc[i][j+0] + bias[col+0];
            r.y = acc[i][j+1] + bias[col+1];
            r.z = acc[i][j+2] + bias[col+2];
            r.w = acc[i][j+3] + bias[col+3];
            *(float4*)&Cout[(((size_t)(b * H_ + h)) * S_ + s) * HD_ + hd] = r;
        }
    }
}

__global__ void __launch_bounds__(256)
out_gemm_kernel(const float* __restrict__ Wo, const float* __restrict__ bo,
                float* __restrict__ out)
{
    const int rowBase = blockIdx.y * BM;
    const int colBase = blockIdx.x * BN;
    float acc[8][8] = {};
    sgemm_tile_768(g_ctx, Wo, rowBase, colBase, acc);

    const int tr = threadIdx.x >> 4;
    const int tc = threadIdx.x & 15;
    #pragma unroll
    for (int i = 0; i < 8; i++) {
        int row = rowBase + (tr << 3) + i;
        #pragma unroll
        for (int j = 0; j < 8; j += 4) {
            int col = colBase + (tc << 3) + j;
            float4 r;
            r.x = acc[i][j+0] + bo[col+0];
            r.y = acc[i][j+1] + bo[col+1];
            r.z = acc[i][j+2] + bo[col+2];
            r.w = acc[i][j+3] + bo[col+3];
            *(float4*)&out[(size_t)row * D_ + col] = r;
        }
    }
}

// ---------------------------------------------------------------------------
// Flash attention with mma.sync tf32.
// 64 q-rows per block, 4 warps (128 threads); each warp owns 16 q-rows.
// Q held in registers as A-fragments (scaled by 1/8, tf32-rounded) for the
// whole kernel. K/V tiles staged in padded smem (stride 68 => conflict-free
// fragment gathers). P re-staged per-warp through smem to convert the C-frag
// layout (cols 2t,2t+1) into the A-frag layout (cols t,t+4).
// Smem: Ks[64][68] + Vs[64][68] + Ps[4][16][68] = 52224 B (dynamic).
// ---------------------------------------------------------------------------
#define AQP 68
#define ATT_SMEM ((2 * 64 * AQP + 4 * 16 * AQP) * 4)

__global__ void __launch_bounds__(128) attn_mma_kernel()
{
    extern __shared__ float sm[];
    float* Ks = sm;                    // [64][AQP]  (also Q staging pre-loop)
    float* Vs = sm + 64 * AQP;         // [64][AQP]
    float* Ps = sm + 2 * 64 * AQP;     // [4][16][AQP]

    const int tid  = threadIdx.x;
    const int warp = tid >> 5;
    const int lane = tid & 31;
    const int g    = lane >> 2;        // groupID 0..7
    const int t    = lane & 3;         // thread-in-group 0..3
    const int bh   = blockIdx.y;
    const int q0   = blockIdx.x << 6;

    const float* Qb = g_q + (size_t)bh * S_ * HD_;
    const float* Kb = g_k + (size_t)bh * S_ * HD_;
    const float* Vb = g_v + (size_t)bh * S_ * HD_;

    const int lr = tid >> 4;           // loader row 0..7 (stride 8)
    const int lc = (tid & 15) << 2;    // loader col 0..60

    // ---- Stage Q tile (scaled by 1/sqrt(64), tf32-rounded) into Ks ----
    #pragma unroll
    for (int i = 0; i < 8; i++) {
        int row = lr + (i << 3);
        float4 v = *(const float4*)(Qb + (size_t)(q0 + row) * HD_ + lc);
        Ks[row * AQP + lc + 0] = __uint_as_float(tf32r(v.x * 0.125f));
        Ks[row * AQP + lc + 1] = __uint_as_float(tf32r(v.y * 0.125f));
        Ks[row * AQP + lc + 2] = __uint_as_float(tf32r(v.z * 0.125f));
        Ks[row * AQP + lc + 3] = __uint_as_float(tf32r(v.w * 0.125f));
    }
    __syncthreads();

    // ---- Read Q as A-fragments: qf[k_chunk][4] ----
    uint32_t qf[8][4];
    {
        const int r0 = (warp << 4) + g;
        #pragma unroll
        for (int k = 0; k < 8; k++) {
            qf[k][0] = __float_as_uint(Ks[r0       * AQP + (k << 3) + t]);
            qf[k][1] = __float_as_uint(Ks[(r0 + 8) * AQP + (k << 3) + t]);
            qf[k][2] = __float_as_uint(Ks[r0       * AQP + (k << 3) + t + 4]);
            qf[k][3] = __float_as_uint(Ks[(r0 + 8) * AQP + (k << 3) + t + 4]);
        }
    }

    float m0 = -1e30f, m1 = -1e30f, l0 = 0.f, l1 = 0.f;
    float o[8][4];
    #pragma unroll
    for (int n = 0; n < 8; n++)
        #pragma unroll
        for (int j = 0; j < 4; j++) o[n][j] = 0.f;

    float* Pw = Ps + warp * 16 * AQP;

    for (int kt = 0; kt < S_; kt += 64) {
        __syncthreads();   // prior tile's K/V reads complete (incl. Q staging)
        // ---- Load K/V tile (tf32-rounded) ----
        #pragma unroll
        for (int i = 0; i < 8; i++) {
            int row = lr + (i << 3);
            float4 kv = *(const float4*)(Kb + (size_t)(kt + row) * HD_ + lc);
            Ks[row * AQP + lc + 0] = __uint_as_float(tf32r(kv.x));
            Ks[row * AQP + lc + 1] = __uint_as_float(tf32r(kv.y));
            Ks[row * AQP + lc + 2] = __uint_as_float(tf32r(kv.z));
            Ks[row * AQP + lc + 3] = __uint_as_float(tf32r(kv.w));
            float4 vv = *(const float4*)(Vb + (size_t)(kt + row) * HD_ + lc);
            Vs[row * AQP + lc + 0] = __uint_as_float(tf32r(vv.x));
            Vs[row * AQP + lc + 1] = __uint_as_float(tf32r(vv.y));
            Vs[row * AQP + lc + 2] = __uint_as_float(tf32r(vv.z));
            Vs[row * AQP + lc + 3] = __uint_as_float(tf32r(vv.w));
        }
        __syncthreads();

        // ---- S = (Q*scale) @ K^T via mma ----
        float sacc[8][4];
        #pragma unroll
        for (int n = 0; n < 8; n++) {
            sacc[n][0] = sacc[n][1] = sacc[n][2] = sacc[n][3] = 0.f;
            const float* kbase = Ks + (((n << 3) + g) * AQP) + t;
            #pragma unroll
            for (int k = 0; k < 8; k++) {
                uint32_t b0 = __float_as_uint(kbase[(k << 3)]);
                uint32_t b1 = __float_as_uint(kbase[(k << 3) + 4]);
                mma_tf32(sacc[n], qf[k], b0, b1);
            }
        }

        // ---- Online softmax (rows r0 = warp*16+g, r1 = r0+8) ----
        float mx0 = -1e30f, mx1 = -1e30f;
        #pragma unroll
        for (int n = 0; n < 8; n++) {
            mx0 = fmaxf(mx0, fmaxf(sacc[n][0], sacc[n][1]));
            mx1 = fmaxf(mx1, fmaxf(sacc[n][2], sacc[n][3]));
        }
        mx0 = fmaxf(mx0, __shfl_xor_sync(0xffffffffu, mx0, 1));
        mx0 = fmaxf(mx0, __shfl_xor_sync(0xffffffffu, mx0, 2));
        mx1 = fmaxf(mx1, __shfl_xor_sync(0xffffffffu, mx1, 1));
        mx1 = fmaxf(mx1, __shfl_xor_sync(0xffffffffu, mx1, 2));

        float mn0 = fmaxf(m0, mx0);
        float mn1 = fmaxf(m1, mx1);
        float al0 = __expf(m0 - mn0);
        float al1 = __expf(m1 - mn1);
        m0 = mn0; m1 = mn1;

        float rs0 = 0.f, rs1 = 0.f;
        #pragma unroll
        for (int n = 0; n < 8; n++) {
            sacc[n][0] = __expf(sacc[n][0] - mn0);
            sacc[n][1] = __expf(sacc[n][1] - mn0);
            sacc[n][2] = __expf(sacc[n][2] - mn1);
            sacc[n][3] = __expf(sacc[n][3] - mn1);
            rs0 += sacc[n][0] + sacc[n][1];
            rs1 += sacc[n][2] + sacc[n][3];
        }
        rs0 += __shfl_xor_sync(0xffffffffu, rs0, 1);
        rs0 += __shfl_xor_sync(0xffffffffu, rs0, 2);
        rs1 += __shfl_xor_sync(0xffffffffu, rs1, 1);
        rs1 += __shfl_xor_sync(0xffffffffu, rs1, 2);
        l0 = l0 * al0 + rs0;
        l1 = l1 * al1 + rs1;

        #pragma unroll
        for (int n = 0; n < 8; n++) {
            o[n][0] *= al0; o[n][1] *= al0;
            o[n][2] *= al1; o[n][3] *= al1;
        }

        // ---- Stage P (tf32-rounded) per warp: C-frag -> smem -> A-frag ----
        #pragma unroll
        for (int n = 0; n < 8; n++) {
            float2 p01, p23;
            p01.x = __uint_as_float(tf32r(sacc[n][0]));
            p01.y = __uint_as_float(tf32r(sacc[n][1]));
            p23.x = __uint_as_float(tf32r(sacc[n][2]));
            p23.y = __uint_as_float(tf32r(sacc[n][3]));
            *(float2*)&Pw[g       * AQP + (n << 3) + (t << 1)] = p01;
            *(float2*)&Pw[(g + 8) * AQP + (n << 3) + (t << 1)] = p23;
        }
        __syncwarp();

        uint32_t pf[8][4];
        #pragma unroll
        for (int k = 0; k < 8; k++) {
            pf[k][0] = __float_as_uint(Pw[g       * AQP + (k << 3) + t]);
            pf[k][1] = __float_as_uint(Pw[(g + 8) * AQP + (k << 3) + t]);
            pf[k][2] = __float_as_uint(Pw[g       * AQP + (k << 3) + t + 4]);
            pf[k][3] = __float_as_uint(Pw[(g + 8) * AQP + (k << 3) + t + 4]);
        }

        // ---- O += P @ V via mma ----
        #pragma unroll
        for (int n = 0; n < 8; n++) {
            const float* vbase = Vs + t * AQP + (n << 3) + g;
            #pragma unroll
            for (int k = 0; k < 8; k++) {
                uint32_t b0 = __float_as_uint(vbase[(k << 3) * AQP]);
                uint32_t b1 = __float_as_uint(vbase[((k << 3) + 4) * AQP]);
                mma_tf32(o[n], pf[k], b0, b1);
            }
        }
    }

    // ---- Epilogue: normalize, write ctx [b,s,d] ----
    const int b  = bh / H_;
    const int h  = bh - b * H_;
    const float inv0 = 1.0f / l0;
    const float inv1 = 1.0f / l1;
    const int sg0 = q0 + (warp << 4) + g;
    const int sg1 = sg0 + 8;
    float* ctx0 = g_ctx + (size_t)(b * S_ + sg0) * D_ + h * HD_;
    float* ctx1 = g_ctx + (size_t)(b * S_ + sg1) * D_ + h * HD_;
    #pragma unroll
    for (int n = 0; n < 8; n++) {
        float2 r0, r1;
        r0.x = o[n][0] * inv0; r0.y = o[n][1] * inv0;
        r1.x = o[n][2] * inv1; r1.y = o[n][3] * inv1;
        *(float2*)&ctx0[(n << 3) + (t << 1)] = r0;
        *(float2*)&ctx1[(n << 3) + (t << 1)] = r1;
    }
}

// ---------------------------------------------------------------------------
// Launch
// ---------------------------------------------------------------------------
extern "C" void kernel_launch(void* const* d_in, const int* in_sizes, int n_in,
                              void* d_out, int out_size)
{
    (void)in_sizes; (void)n_in; (void)out_size;
    const float* x  = (const float*)d_in[0];
    const float* Wq = (const float*)d_in[1];
    const float* bq = (const float*)d_in[2];
    const float* Wk = (const float*)d_in[3];
    const float* bk = (const float*)d_in[4];
    const float* Wv = (const float*)d_in[5];
    const float* bv = (const float*)d_in[6];
    const float* Wo = (const float*)d_in[7];
    const float* bo = (const float*)d_in[8];
    float* out = (float*)d_out;

    cudaFuncSetAttribute(attn_mma_kernel,
                         cudaFuncAttributeMaxDynamicSharedMemorySize, ATT_SMEM);

    qkv_gemm_kernel<<<dim3(D_/BN, M_/BM, 3), 256>>>(x, Wq, bq, Wk, bk, Wv, bv);
    attn_mma_kernel<<<dim3(S_/64, B_*H_), 128, ATT_SMEM>>>();
    out_gemm_kernel<<<dim3(D_/BN, M_/BM), 256>>>(Wo, bo, out);
}

// round 7
// speedup vs baseline: 2.9565x; 1.6719x over previous
#include <cuda_runtime.h>
#include <math.h>
#include <stdint.h>

// Problem constants
#define B_  2
#define S_  2048
#define D_  768
#define H_  12
#define HD_ 64
#define M_  (B_*S_)   // 4096

// ---------------------------------------------------------------------------
// Device scratch (allocation-free rule: static __device__ arrays)
// ---------------------------------------------------------------------------
__device__ float g_q[B_*H_*S_*HD_];    // [b,h,s,hd]
__device__ float g_k[B_*H_*S_*HD_];
__device__ float g_v[B_*H_*S_*HD_];
__device__ float g_ctx[M_*D_];         // [b,s,d]

// ---------------------------------------------------------------------------
// Helpers: tf32 rounding + mma.sync
// ---------------------------------------------------------------------------
__device__ __forceinline__ uint32_t tf32r(float x) {
    uint32_t u;
    asm("cvt.rna.tf32.f32 %0, %1;" : "=r"(u) : "f"(x));
    return u;
}

__device__ __forceinline__ float4 tf32r4(float4 v) {
    v.x = __uint_as_float(tf32r(v.x));
    v.y = __uint_as_float(tf32r(v.y));
    v.z = __uint_as_float(tf32r(v.z));
    v.w = __uint_as_float(tf32r(v.w));
    return v;
}

__device__ __forceinline__ void mma_tf32(float c[4], const uint32_t a[4],
                                         uint32_t b0, uint32_t b1) {
    asm volatile(
        "mma.sync.aligned.m16n8k8.row.col.f32.tf32.tf32.f32 "
        "{%0,%1,%2,%3},{%4,%5,%6,%7},{%8,%9},{%0,%1,%2,%3};"
        : "+f"(c[0]), "+f"(c[1]), "+f"(c[2]), "+f"(c[3])
        : "r"(a[0]), "r"(a[1]), "r"(a[2]), "r"(a[3]), "r"(b0), "r"(b1));
}

// ---------------------------------------------------------------------------
// tf32 tensor-core GEMM: C[128x128] tile, BK=16, 256 threads (8 warps).
// Warp grid 2(m) x 4(n): each warp owns 64x32 = 4x4 m16n8 tiles.
// As[m][k] stride 20  -> A-frag reads bank-conflict-free (g*20+t distinct).
// Bs[k][n] stride 136 -> B-frag reads bank-conflict-free (t*8+g distinct).
// Operands rna-rounded to tf32 on the global->smem path.
// ---------------------------------------------------------------------------
#define BM 128
#define BN 128
#define BKK 16
#define GAP 20    // As row stride
#define GBP 136   // Bs row stride

__device__ __forceinline__ void tf32_gemm_tile(
    const float* __restrict__ A, const float* __restrict__ W,
    int rowBase, int colBase, float acc[16][4])
{
    __shared__ float As[BM][GAP];
    __shared__ float Bs[BKK][GBP];

    const int tid  = threadIdx.x;
    const int lane = tid & 31;
    const int warp = tid >> 5;
    const int g    = lane >> 2;      // 0..7
    const int t    = lane & 3;       // 0..3
    const int wm   = warp >> 2;      // 0..1  (64 rows each)
    const int wn   = warp & 3;       // 0..3  (32 cols each)

    // A loader: 128x16 = 512 float4, 2 per thread
    const int ar = tid >> 2;             // 0..63
    const int ak = (tid & 3) << 2;       // 0,4,8,12
    // B loader: 16x128 = 512 float4, 2 per thread
    const int br = tid >> 5;             // 0..7
    const int bc = (tid & 31) << 2;      // 0..124

    const float* Ap0 = A + (size_t)(rowBase + ar) * D_ + ak;
    const float* Ap1 = Ap0 + (size_t)64 * D_;
    const float* Wp0 = W + (size_t)br * D_ + colBase + bc;
    const float* Wp1 = Wp0 + (size_t)8 * D_;

    for (int k0 = 0; k0 < D_; k0 += BKK) {
        float4 a0 = *(const float4*)(Ap0 + k0);
        float4 a1 = *(const float4*)(Ap1 + k0);
        float4 b0 = *(const float4*)(Wp0 + (size_t)k0 * D_);
        float4 b1 = *(const float4*)(Wp1 + (size_t)k0 * D_);
        __syncthreads();   // previous iteration's fragment reads complete
        *(float4*)&As[ar][ak]      = tf32r4(a0);
        *(float4*)&As[ar + 64][ak] = tf32r4(a1);
        *(float4*)&Bs[br][bc]      = tf32r4(b0);
        *(float4*)&Bs[br + 8][bc]  = tf32r4(b1);
        __syncthreads();

        #pragma unroll
        for (int ks = 0; ks < BKK; ks += 8) {
            uint32_t af[4][4], bf[4][2];
            #pragma unroll
            for (int mt = 0; mt < 4; mt++) {
                const int m0 = (wm << 6) + (mt << 4);
                af[mt][0] = __float_as_uint(As[m0 + g    ][ks + t    ]);
                af[mt][1] = __float_as_uint(As[m0 + g + 8][ks + t    ]);
                af[mt][2] = __float_as_uint(As[m0 + g    ][ks + t + 4]);
                af[mt][3] = __float_as_uint(As[m0 + g + 8][ks + t + 4]);
            }
            #pragma unroll
            for (int nt = 0; nt < 4; nt++) {
                const int n0 = (wn << 5) + (nt << 3);
                bf[nt][0] = __float_as_uint(Bs[ks + t    ][n0 + g]);
                bf[nt][1] = __float_as_uint(Bs[ks + t + 4][n0 + g]);
            }
            #pragma unroll
            for (int mt = 0; mt < 4; mt++)
                #pragma unroll
                for (int nt = 0; nt < 4; nt++)
                    mma_tf32(acc[mt * 4 + nt], af[mt], bf[nt][0], bf[nt][1]);
        }
    }
}

// ---------------------------------------------------------------------------
// QKV projection -> head layout [b,h,s,hd]; grid (6, 32, 3)
// ---------------------------------------------------------------------------
__global__ void __launch_bounds__(256)
qkv_gemm_kernel(const float* __restrict__ x,
                const float* __restrict__ Wq, const float* __restrict__ bq,
                const float* __restrict__ Wk, const float* __restrict__ bk,
                const float* __restrict__ Wv, const float* __restrict__ bv)
{
    const float* W; const float* bias; float* Cout;
    if (blockIdx.z == 0)      { W = Wq; bias = bq; Cout = g_q; }
    else if (blockIdx.z == 1) { W = Wk; bias = bk; Cout = g_k; }
    else                      { W = Wv; bias = bv; Cout = g_v; }

    const int rowBase = blockIdx.y * BM;
    const int colBase = blockIdx.x * BN;
    float acc[16][4];
    #pragma unroll
    for (int i = 0; i < 16; i++)
        acc[i][0] = acc[i][1] = acc[i][2] = acc[i][3] = 0.f;

    tf32_gemm_tile(x, W, rowBase, colBase, acc);

    const int lane = threadIdx.x & 31;
    const int warp = threadIdx.x >> 5;
    const int g = lane >> 2, t = lane & 3;
    const int wm = warp >> 2, wn = warp & 3;

    #pragma unroll
    for (int mt = 0; mt < 4; mt++) {
        #pragma unroll
        for (int nt = 0; nt < 4; nt++) {
            const float* c = acc[mt * 4 + nt];
            const int col = colBase + (wn << 5) + (nt << 3) + (t << 1);
            const int h = col >> 6, hd = col & 63;
            const float bx = bias[col], by = bias[col + 1];
            #pragma unroll
            for (int rr = 0; rr < 2; rr++) {
                const int row = rowBase + (wm << 6) + (mt << 4) + g + (rr << 3);
                const int b = row >> 11;
                const int s = row & (S_ - 1);
                float2 r;
                r.x = c[rr * 2 + 0] + bx;
                r.y = c[rr * 2 + 1] + by;
                *(float2*)&Cout[(((size_t)(b * H_ + h)) * S_ + s) * HD_ + hd] = r;
            }
        }
    }
}

// ---------------------------------------------------------------------------
// Output projection: out = ctx @ Wo + bo, [b,s,d]
// ---------------------------------------------------------------------------
__global__ void __launch_bounds__(256)
out_gemm_kernel(const float* __restrict__ Wo, const float* __restrict__ bo,
                float* __restrict__ out)
{
    const int rowBase = blockIdx.y * BM;
    const int colBase = blockIdx.x * BN;
    float acc[16][4];
    #pragma unroll
    for (int i = 0; i < 16; i++)
        acc[i][0] = acc[i][1] = acc[i][2] = acc[i][3] = 0.f;

    tf32_gemm_tile(g_ctx, Wo, rowBase, colBase, acc);

    const int lane = threadIdx.x & 31;
    const int warp = threadIdx.x >> 5;
    const int g = lane >> 2, t = lane & 3;
    const int wm = warp >> 2, wn = warp & 3;

    #pragma unroll
    for (int mt = 0; mt < 4; mt++) {
        #pragma unroll
        for (int nt = 0; nt < 4; nt++) {
            const float* c = acc[mt * 4 + nt];
            const int col = colBase + (wn << 5) + (nt << 3) + (t << 1);
            const float bx = bo[col], by = bo[col + 1];
            #pragma unroll
            for (int rr = 0; rr < 2; rr++) {
                const int row = rowBase + (wm << 6) + (mt << 4) + g + (rr << 3);
                float2 r;
                r.x = c[rr * 2 + 0] + bx;
                r.y = c[rr * 2 + 1] + by;
                *(float2*)&out[(size_t)row * D_ + col] = r;
            }
        }
    }
}

// ---------------------------------------------------------------------------
// Flash attention with mma.sync tf32 (unchanged from R4 — proven at ~320us,
// rel_err contribution ~1e-4).
// ---------------------------------------------------------------------------
#define AQP 68
#define ATT_SMEM ((2 * 64 * AQP + 4 * 16 * AQP) * 4)

__global__ void __launch_bounds__(128) attn_mma_kernel()
{
    extern __shared__ float sm[];
    float* Ks = sm;                    // [64][AQP]  (also Q staging pre-loop)
    float* Vs = sm + 64 * AQP;         // [64][AQP]
    float* Ps = sm + 2 * 64 * AQP;     // [4][16][AQP]

    const int tid  = threadIdx.x;
    const int warp = tid >> 5;
    const int lane = tid & 31;
    const int g    = lane >> 2;
    const int t    = lane & 3;
    const int bh   = blockIdx.y;
    const int q0   = blockIdx.x << 6;

    const float* Qb = g_q + (size_t)bh * S_ * HD_;
    const float* Kb = g_k + (size_t)bh * S_ * HD_;
    const float* Vb = g_v + (size_t)bh * S_ * HD_;

    const int lr = tid >> 4;
    const int lc = (tid & 15) << 2;

    #pragma unroll
    for (int i = 0; i < 8; i++) {
        int row = lr + (i << 3);
        float4 v = *(const float4*)(Qb + (size_t)(q0 + row) * HD_ + lc);
        Ks[row * AQP + lc + 0] = __uint_as_float(tf32r(v.x * 0.125f));
        Ks[row * AQP + lc + 1] = __uint_as_float(tf32r(v.y * 0.125f));
        Ks[row * AQP + lc + 2] = __uint_as_float(tf32r(v.z * 0.125f));
        Ks[row * AQP + lc + 3] = __uint_as_float(tf32r(v.w * 0.125f));
    }
    __syncthreads();

    uint32_t qf[8][4];
    {
        const int r0 = (warp << 4) + g;
        #pragma unroll
        for (int k = 0; k < 8; k++) {
            qf[k][0] = __float_as_uint(Ks[r0       * AQP + (k << 3) + t]);
            qf[k][1] = __float_as_uint(Ks[(r0 + 8) * AQP + (k << 3) + t]);
            qf[k][2] = __float_as_uint(Ks[r0       * AQP + (k << 3) + t + 4]);
            qf[k][3] = __float_as_uint(Ks[(r0 + 8) * AQP + (k << 3) + t + 4]);
        }
    }

    float m0 = -1e30f, m1 = -1e30f, l0 = 0.f, l1 = 0.f;
    float o[8][4];
    #pragma unroll
    for (int n = 0; n < 8; n++)
        #pragma unroll
        for (int j = 0; j < 4; j++) o[n][j] = 0.f;

    float* Pw = Ps + warp * 16 * AQP;

    for (int kt = 0; kt < S_; kt += 64) {
        __syncthreads();
        #pragma unroll
        for (int i = 0; i < 8; i++) {
            int row = lr + (i << 3);
            float4 kv = *(const float4*)(Kb + (size_t)(kt + row) * HD_ + lc);
            Ks[row * AQP + lc + 0] = __uint_as_float(tf32r(kv.x));
            Ks[row * AQP + lc + 1] = __uint_as_float(tf32r(kv.y));
            Ks[row * AQP + lc + 2] = __uint_as_float(tf32r(kv.z));
            Ks[row * AQP + lc + 3] = __uint_as_float(tf32r(kv.w));
            float4 vv = *(const float4*)(Vb + (size_t)(kt + row) * HD_ + lc);
            Vs[row * AQP + lc + 0] = __uint_as_float(tf32r(vv.x));
            Vs[row * AQP + lc + 1] = __uint_as_float(tf32r(vv.y));
            Vs[row * AQP + lc + 2] = __uint_as_float(tf32r(vv.z));
            Vs[row * AQP + lc + 3] = __uint_as_float(tf32r(vv.w));
        }
        __syncthreads();

        float sacc[8][4];
        #pragma unroll
        for (int n = 0; n < 8; n++) {
            sacc[n][0] = sacc[n][1] = sacc[n][2] = sacc[n][3] = 0.f;
            const float* kbase = Ks + (((n << 3) + g) * AQP) + t;
            #pragma unroll
            for (int k = 0; k < 8; k++) {
                uint32_t b0 = __float_as_uint(kbase[(k << 3)]);
                uint32_t b1 = __float_as_uint(kbase[(k << 3) + 4]);
                mma_tf32(sacc[n], qf[k], b0, b1);
            }
        }

        float mx0 = -1e30f, mx1 = -1e30f;
        #pragma unroll
        for (int n = 0; n < 8; n++) {
            mx0 = fmaxf(mx0, fmaxf(sacc[n][0], sacc[n][1]));
            mx1 = fmaxf(mx1, fmaxf(sacc[n][2], sacc[n][3]));
        }
        mx0 = fmaxf(mx0, __shfl_xor_sync(0xffffffffu, mx0, 1));
        mx0 = fmaxf(mx0, __shfl_xor_sync(0xffffffffu, mx0, 2));
        mx1 = fmaxf(mx1, __shfl_xor_sync(0xffffffffu, mx1, 1));
        mx1 = fmaxf(mx1, __shfl_xor_sync(0xffffffffu, mx1, 2));

        float mn0 = fmaxf(m0, mx0);
        float mn1 = fmaxf(m1, mx1);
        float al0 = __expf(m0 - mn0);
        float al1 = __expf(m1 - mn1);
        m0 = mn0; m1 = mn1;

        float rs0 = 0.f, rs1 = 0.f;
        #pragma unroll
        for (int n = 0; n < 8; n++) {
            sacc[n][0] = __expf(sacc[n][0] - mn0);
            sacc[n][1] = __expf(sacc[n][1] - mn0);
            sacc[n][2] = __expf(sacc[n][2] - mn1);
            sacc[n][3] = __expf(sacc[n][3] - mn1);
            rs0 += sacc[n][0] + sacc[n][1];
            rs1 += sacc[n][2] + sacc[n][3];
        }
        rs0 += __shfl_xor_sync(0xffffffffu, rs0, 1);
        rs0 += __shfl_xor_sync(0xffffffffu, rs0, 2);
        rs1 += __shfl_xor_sync(0xffffffffu, rs1, 1);
        rs1 += __shfl_xor_sync(0xffffffffu, rs1, 2);
        l0 = l0 * al0 + rs0;
        l1 = l1 * al1 + rs1;

        #pragma unroll
        for (int n = 0; n < 8; n++) {
            o[n][0] *= al0; o[n][1] *= al0;
            o[n][2] *= al1; o[n][3] *= al1;
        }

        #pragma unroll
        for (int n = 0; n < 8; n++) {
            float2 p01, p23;
            p01.x = __uint_as_float(tf32r(sacc[n][0]));
            p01.y = __uint_as_float(tf32r(sacc[n][1]));
            p23.x = __uint_as_float(tf32r(sacc[n][2]));
            p23.y = __uint_as_float(tf32r(sacc[n][3]));
            *(float2*)&Pw[g       * AQP + (n << 3) + (t << 1)] = p01;
            *(float2*)&Pw[(g + 8) * AQP + (n << 3) + (t << 1)] = p23;
        }
        __syncwarp();

        uint32_t pf[8][4];
        #pragma unroll
        for (int k = 0; k < 8; k++) {
            pf[k][0] = __float_as_uint(Pw[g       * AQP + (k << 3) + t]);
            pf[k][1] = __float_as_uint(Pw[(g + 8) * AQP + (k << 3) + t]);
            pf[k][2] = __float_as_uint(Pw[g       * AQP + (k << 3) + t + 4]);
            pf[k][3] = __float_as_uint(Pw[(g + 8) * AQP + (k << 3) + t + 4]);
        }

        #pragma unroll
        for (int n = 0; n < 8; n++) {
            const float* vbase = Vs + t * AQP + (n << 3) + g;
            #pragma unroll
            for (int k = 0; k < 8; k++) {
                uint32_t b0 = __float_as_uint(vbase[(k << 3) * AQP]);
                uint32_t b1 = __float_as_uint(vbase[((k << 3) + 4) * AQP]);
                mma_tf32(o[n], pf[k], b0, b1);
            }
        }
    }

    const int b  = bh / H_;
    const int h  = bh - b * H_;
    const float inv0 = 1.0f / l0;
    const float inv1 = 1.0f / l1;
    const int sg0 = q0 + (warp << 4) + g;
    const int sg1 = sg0 + 8;
    float* ctx0 = g_ctx + (size_t)(b * S_ + sg0) * D_ + h * HD_;
    float* ctx1 = g_ctx + (size_t)(b * S_ + sg1) * D_ + h * HD_;
    #pragma unroll
    for (int n = 0; n < 8; n++) {
        float2 r0, r1;
        r0.x = o[n][0] * inv0; r0.y = o[n][1] * inv0;
        r1.x = o[n][2] * inv1; r1.y = o[n][3] * inv1;
        *(float2*)&ctx0[(n << 3) + (t << 1)] = r0;
        *(float2*)&ctx1[(n << 3) + (t << 1)] = r1;
    }
}

// ---------------------------------------------------------------------------
// Launch
// ---------------------------------------------------------------------------
extern "C" void kernel_launch(void* const* d_in, const int* in_sizes, int n_in,
                              void* d_out, int out_size)
{
    (void)in_sizes; (void)n_in; (void)out_size;
    const float* x  = (const float*)d_in[0];
    const float* Wq = (const float*)d_in[1];
    const float* bq = (const float*)d_in[2];
    const float* Wk = (const float*)d_in[3];
    const float* bk = (const float*)d_in[4];
    const float* Wv = (const float*)d_in[5];
    const float* bv = (const float*)d_in[6];
    const float* Wo = (const float*)d_in[7];
    const float* bo = (const float*)d_in[8];
    float* out = (float*)d_out;

    cudaFuncSetAttribute(attn_mma_kernel,
                         cudaFuncAttributeMaxDynamicSharedMemorySize, ATT_SMEM);

    qkv_gemm_kernel<<<dim3(D_/BN, M_/BM, 3), 256>>>(x, Wq, bq, Wk, bk, Wv, bv);
    attn_mma_kernel<<<dim3(S_/64, B_*H_), 128, ATT_SMEM>>>();
    out_gemm_kernel<<<dim3(D_/BN, M_/BM), 256>>>(Wo, bo, out);
}

// round 10
// speedup vs baseline: 3.5024x; 1.1847x over previous
#include <cuda_runtime.h>
#include <math.h>
#include <stdint.h>

// Problem constants
#define B_  2
#define S_  2048
#define D_  768
#define H_  12
#define HD_ 64
#define M_  (B_*S_)   // 4096

// ---------------------------------------------------------------------------
// Device scratch (allocation-free rule: static __device__ arrays)
// ---------------------------------------------------------------------------
__device__ float g_q[B_*H_*S_*HD_];    // [b,h,s,hd]   (tf32-rounded values)
__device__ float g_k[B_*H_*S_*HD_];
__device__ float g_v[B_*H_*S_*HD_];
__device__ float g_ctx[M_*D_];         // [b,s,d]      (tf32-rounded values)
__device__ float g_xr[M_*D_];          // tf32-rounded x
__device__ float g_wr[4][D_*D_];       // tf32-rounded Wq,Wk,Wv,Wo

// ---------------------------------------------------------------------------
// Helpers
// ---------------------------------------------------------------------------
__device__ __forceinline__ uint32_t tf32r(float x) {
    uint32_t u;
    asm("cvt.rna.tf32.f32 %0, %1;" : "=r"(u) : "f"(x));
    return u;
}
__device__ __forceinline__ float tf32rf(float x) {
    return __uint_as_float(tf32r(x));
}
__device__ __forceinline__ float4 tf32r4(float4 v) {
    v.x = tf32rf(v.x); v.y = tf32rf(v.y);
    v.z = tf32rf(v.z); v.w = tf32rf(v.w);
    return v;
}

__device__ __forceinline__ void mma_tf32(float c[4], const uint32_t a[4],
                                         uint32_t b0, uint32_t b1) {
    asm volatile(
        "mma.sync.aligned.m16n8k8.row.col.f32.tf32.tf32.f32 "
        "{%0,%1,%2,%3},{%4,%5,%6,%7},{%8,%9},{%0,%1,%2,%3};"
        : "+f"(c[0]), "+f"(c[1]), "+f"(c[2]), "+f"(c[3])
        : "r"(a[0]), "r"(a[1]), "r"(a[2]), "r"(a[3]), "r"(b0), "r"(b1));
}

__device__ __forceinline__ void cp16(uint32_t dst, const void* src) {
    asm volatile("cp.async.cg.shared.global [%0], [%1], 16;"
                 :: "r"(dst), "l"(src) : "memory");
}
__device__ __forceinline__ void cp_commit() {
    asm volatile("cp.async.commit_group;" ::: "memory");
}
template<int N> __device__ __forceinline__ void cp_wait() {
    asm volatile("cp.async.wait_group %0;" :: "n"(N) : "memory");
}

// ---------------------------------------------------------------------------
// Pre-round pass: RNA-round x and the 4 weight matrices into scratch.
// Flattened float4 index space: x (786432) then 4 x W (147456 each).
// ---------------------------------------------------------------------------
#define N4_X (M_*D_/4)       // 786432
#define N4_W (D_*D_/4)       // 147456
#define N4_TOTAL (N4_X + 4*N4_W)

__global__ void __launch_bounds__(256)
round_all_kernel(const float4* __restrict__ x,
                 const float4* __restrict__ Wq, const float4* __restrict__ Wk,
                 const float4* __restrict__ Wv, const float4* __restrict__ Wo)
{
    int i = blockIdx.x * 256 + threadIdx.x;
    if (i >= N4_TOTAL) return;
    if (i < N4_X) {
        ((float4*)g_xr)[i] = tf32r4(x[i]);
    } else {
        int j = i - N4_X;
        int w = j / N4_W;
        int o = j - w * N4_W;
        const float4* src = (w == 0) ? Wq : (w == 1) ? Wk : (w == 2) ? Wv : Wo;
        ((float4*)g_wr[w])[o] = tf32r4(src[o]);
    }
}

// ---------------------------------------------------------------------------
// tf32 tensor-core GEMM, cp.async double-buffered, operands pre-rounded.
// C tile 128x128, BK=16, 256 threads (8 warps, 2m x 4n).
// As[m][20]: A-frag banks 20g+t distinct. Bs[k][136]: banks 8t+g distinct.
// ---------------------------------------------------------------------------
#define BM 128
#define BN 128
#define BKK 16
#define GAP 20
#define GBP 136
#define ABUF (BM*GAP)          // 2560 floats
#define BBUF (BKK*GBP)         // 2176 floats
#define GSM  (2*ABUF + 2*BBUF) // 9472 floats = 37888 B

__device__ __forceinline__ void tf32_gemm_tile(
    const float* __restrict__ A, const float* __restrict__ W,
    int rowBase, int colBase, float acc[16][4])
{
    __shared__ float smg[GSM];
    const uint32_t sb = (uint32_t)__cvta_generic_to_shared(smg);

    const int tid  = threadIdx.x;
    const int lane = tid & 31;
    const int warp = tid >> 5;
    const int g    = lane >> 2;
    const int t    = lane & 3;
    const int wm   = warp >> 2;
    const int wn   = warp & 3;

    const int ar = tid >> 2;             // 0..63
    const int ak = (tid & 3) << 2;       // 0,4,8,12
    const int br = tid >> 5;             // 0..7
    const int bc = (tid & 31) << 2;      // 0..124

    const float* Ap0 = A + (size_t)(rowBase + ar) * D_ + ak;
    const float* Ap1 = Ap0 + (size_t)64 * D_;
    const float* Wp0 = W + (size_t)br * D_ + colBase + bc;
    const float* Wp1 = Wp0 + (size_t)8 * D_;

    const uint32_t aAddr0[2] = { sb + (uint32_t)((ar * GAP + ak) * 4),
                                 sb + (uint32_t)((ABUF + ar * GAP + ak) * 4) };
    const uint32_t aAddr1[2] = { aAddr0[0] + 64u * GAP * 4u,
                                 aAddr0[1] + 64u * GAP * 4u };
    const uint32_t bAddr0[2] = { sb + (uint32_t)((2*ABUF + br * GBP + bc) * 4),
                                 sb + (uint32_t)((2*ABUF + BBUF + br * GBP + bc) * 4) };
    const uint32_t bAddr1[2] = { bAddr0[0] + 8u * GBP * 4u,
                                 bAddr0[1] + 8u * GBP * 4u };

    cp16(aAddr0[0], Ap0); cp16(aAddr1[0], Ap1);
    cp16(bAddr0[0], Wp0); cp16(bAddr1[0], Wp1);
    cp_commit();

    const int NI = D_ / BKK;   // 48
    int cur = 0;
    for (int it = 0; it < NI; it++) {
        if (it + 1 < NI) {
            const int k0 = (it + 1) * BKK;
            const int nb = cur ^ 1;
            cp16(aAddr0[nb], Ap0 + k0); cp16(aAddr1[nb], Ap1 + k0);
            cp16(bAddr0[nb], Wp0 + (size_t)k0 * D_);
            cp16(bAddr1[nb], Wp1 + (size_t)k0 * D_);
            cp_commit();
            cp_wait<1>();
        } else {
            cp_wait<0>();
        }
        __syncthreads();

        const float (*As)[GAP] = (const float(*)[GAP])(smg + cur * ABUF);
        const float (*Bs)[GBP] = (const float(*)[GBP])(smg + 2*ABUF + cur * BBUF);

        #pragma unroll
        for (int ks = 0; ks < BKK; ks += 8) {
            uint32_t af[4][4], bf[4][2];
            #pragma unroll
            for (int mt = 0; mt < 4; mt++) {
                const int m0 = (wm << 6) + (mt << 4);
                af[mt][0] = __float_as_uint(As[m0 + g    ][ks + t    ]);
                af[mt][1] = __float_as_uint(As[m0 + g + 8][ks + t    ]);
                af[mt][2] = __float_as_uint(As[m0 + g    ][ks + t + 4]);
                af[mt][3] = __float_as_uint(As[m0 + g + 8][ks + t + 4]);
            }
            #pragma unroll
            for (int nt = 0; nt < 4; nt++) {
                const int n0 = (wn << 5) + (nt << 3);
                bf[nt][0] = __float_as_uint(Bs[ks + t    ][n0 + g]);
                bf[nt][1] = __float_as_uint(Bs[ks + t + 4][n0 + g]);
            }
            #pragma unroll
            for (int mt = 0; mt < 4; mt++)
                #pragma unroll
                for (int nt = 0; nt < 4; nt++)
                    mma_tf32(acc[mt * 4 + nt], af[mt], bf[nt][0], bf[nt][1]);
        }
        __syncthreads();
        cur ^= 1;
    }
}

// ---------------------------------------------------------------------------
// QKV projection -> head layout [b,h,s,hd]; writes tf32-rounded values so the
// attention kernel's cp.async path sees exactly-rounded operands.
// ---------------------------------------------------------------------------
__global__ void __launch_bounds__(256)
qkv_gemm_kernel(const float* __restrict__ bq, const float* __restrict__ bk,
                const float* __restrict__ bv)
{
    const float* W; const float* bias; float* Cout;
    if (blockIdx.z == 0)      { W = g_wr[0]; bias = bq; Cout = g_q; }
    else if (blockIdx.z == 1) { W = g_wr[1]; bias = bk; Cout = g_k; }
    else                      { W = g_wr[2]; bias = bv; Cout = g_v; }

    const int rowBase = blockIdx.y * BM;
    const int colBase = blockIdx.x * BN;
    float acc[16][4];
    #pragma unroll
    for (int i = 0; i < 16; i++)
        acc[i][0] = acc[i][1] = acc[i][2] = acc[i][3] = 0.f;

    tf32_gemm_tile(g_xr, W, rowBase, colBase, acc);

    const int lane = threadIdx.x & 31;
    const int warp = threadIdx.x >> 5;
    const int g = lane >> 2, t = lane & 3;
    const int wm = warp >> 2, wn = warp & 3;

    #pragma unroll
    for (int mt = 0; mt < 4; mt++) {
        #pragma unroll
        for (int nt = 0; nt < 4; nt++) {
            const float* c = acc[mt * 4 + nt];
            const int col = colBase + (wn << 5) + (nt << 3) + (t << 1);
            const int h = col >> 6, hd = col & 63;
            const float bx = bias[col], by = bias[col + 1];
            #pragma unroll
            for (int rr = 0; rr < 2; rr++) {
                const int row = rowBase + (wm << 6) + (mt << 4) + g + (rr << 3);
                const int b = row >> 11;
                const int s = row & (S_ - 1);
                float2 r;
                r.x = tf32rf(c[rr * 2 + 0] + bx);
                r.y = tf32rf(c[rr * 2 + 1] + by);
                *(float2*)&Cout[(((size_t)(b * H_ + h)) * S_ + s) * HD_ + hd] = r;
            }
        }
    }
}

// ---------------------------------------------------------------------------
// Output projection: out = ctx @ Wo + bo, [b,s,d] (final, fp32 bias add)
// ---------------------------------------------------------------------------
__global__ void __launch_bounds__(256)
out_gemm_kernel(const float* __restrict__ bo, float* __restrict__ out)
{
    const int rowBase = blockIdx.y * BM;
    const int colBase = blockIdx.x * BN;
    float acc[16][4];
    #pragma unroll
    for (int i = 0; i < 16; i++)
        acc[i][0] = acc[i][1] = acc[i][2] = acc[i][3] = 0.f;

    tf32_gemm_tile(g_ctx, g_wr[3], rowBase, colBase, acc);

    const int lane = threadIdx.x & 31;
    const int warp = threadIdx.x >> 5;
    const int g = lane >> 2, t = lane & 3;
    const int wm = warp >> 2, wn = warp & 3;

    #pragma unroll
    for (int mt = 0; mt < 4; mt++) {
        #pragma unroll
        for (int nt = 0; nt < 4; nt++) {
            const float* c = acc[mt * 4 + nt];
            const int col = colBase + (wn << 5) + (nt << 3) + (t << 1);
            const float bx = bo[col], by = bo[col + 1];
            #pragma unroll
            for (int rr = 0; rr < 2; rr++) {
                const int row = rowBase + (wm << 6) + (mt << 4) + g + (rr << 3);
                float2 r;
                r.x = c[rr * 2 + 0] + bx;
                r.y = c[rr * 2 + 1] + by;
                *(float2*)&out[(size_t)row * D_ + col] = r;
            }
        }
    }
}

// ---------------------------------------------------------------------------
// Flash attention, mma.sync tf32, 128 q-rows/CTA (8 warps, 16 rows each),
// cp.async double-buffered 64-key K/V tiles. K/V/Q arrive pre-rounded from
// qkv_gemm; Q scale 1/8 is exact; P RNA-rounded in registers; ctx written
// tf32-rounded for the out_gemm cp.async path.
// Smem floats: Kbuf[2][64*68] | Vbuf[2][64*72] | Ps[128*68]
// ---------------------------------------------------------------------------
#define KSTR 68
#define VSTR 72
#define KBUF (64*KSTR)             // 4352
#define VBUF (64*VSTR)             // 4608
#define POFF (2*KBUF + 2*VBUF)     // 17920
#define ATT_FLOATS (POFF + 128*KSTR)
#define ATT_SMEM (ATT_FLOATS * 4)  // 106496 B

__global__ void __launch_bounds__(256) attn_mma_kernel()
{
    extern __shared__ float smf[];
    const uint32_t sb = (uint32_t)__cvta_generic_to_shared(smf);
    float* Ps = smf + POFF;

    const int tid  = threadIdx.x;
    const int warp = tid >> 5;
    const int lane = tid & 31;
    const int g    = lane >> 2;
    const int t    = lane & 3;
    const int bh   = blockIdx.y;
    const int q0   = blockIdx.x << 7;          // 128 q-rows per CTA

    const float* Qb = g_q + (size_t)bh * S_ * HD_;
    const float* Kb = g_k + (size_t)bh * S_ * HD_;
    const float* Vb = g_v + (size_t)bh * S_ * HD_;

    const int lr = tid >> 4;                   // 0..15
    const int lc = (tid & 15) << 2;            // 0..60

    uint32_t kAddr[2][4], vAddr[2][4];
    #pragma unroll
    for (int i = 0; i < 4; i++) {
        const int row = lr + (i << 4);
        kAddr[0][i] = sb + (uint32_t)((row * KSTR + lc) * 4);
        kAddr[1][i] = kAddr[0][i] + (uint32_t)(KBUF * 4);
        vAddr[0][i] = sb + (uint32_t)((2*KBUF + row * VSTR + lc) * 4);
        vAddr[1][i] = vAddr[0][i] + (uint32_t)(VBUF * 4);
    }

    // prologue: async-stage tile 0 into buffer 0
    #pragma unroll
    for (int i = 0; i < 4; i++) {
        const int row = lr + (i << 4);
        cp16(kAddr[0][i], Kb + (size_t)row * HD_ + lc);
        cp16(vAddr[0][i], Vb + (size_t)row * HD_ + lc);
    }
    cp_commit();

    // Stage Q (scaled 1/8 — exact; values already tf32) into Ps
    #pragma unroll
    for (int i = 0; i < 8; i++) {
        const int row = lr + (i << 4);
        float4 v = *(const float4*)(Qb + (size_t)(q0 + row) * HD_ + lc);
        Ps[row * KSTR + lc + 0] = v.x * 0.125f;
        Ps[row * KSTR + lc + 1] = v.y * 0.125f;
        Ps[row * KSTR + lc + 2] = v.z * 0.125f;
        Ps[row * KSTR + lc + 3] = v.w * 0.125f;
    }
    __syncthreads();

    // Read Q A-fragments (held for the whole kernel)
    uint32_t qf[8][4];
    {
        const int r0 = (warp << 4) + g;
        #pragma unroll
        for (int k = 0; k < 8; k++) {
            qf[k][0] = __float_as_uint(Ps[r0       * KSTR + (k << 3) + t]);
            qf[k][1] = __float_as_uint(Ps[(r0 + 8) * KSTR + (k << 3) + t]);
            qf[k][2] = __float_as_uint(Ps[r0       * KSTR + (k << 3) + t + 4]);
            qf[k][3] = __float_as_uint(Ps[(r0 + 8) * KSTR + (k << 3) + t + 4]);
        }
    }

    float m0 = -1e30f, m1 = -1e30f, l0 = 0.f, l1 = 0.f;
    float o[8][4];
    #pragma unroll
    for (int n = 0; n < 8; n++)
        #pragma unroll
        for (int j = 0; j < 4; j++) o[n][j] = 0.f;

    float* Pw = Ps + warp * 16 * KSTR;
    int cur = 0;

    for (int kt = 0; kt < S_; kt += 64) {
        if (kt + 64 < S_) {
            const int nb = cur ^ 1;
            #pragma unroll
            for (int i = 0; i < 4; i++) {
                const int row = lr + (i << 4);
                cp16(kAddr[nb][i], Kb + (size_t)(kt + 64 + row) * HD_ + lc);
                cp16(vAddr[nb][i], Vb + (size_t)(kt + 64 + row) * HD_ + lc);
            }
            cp_commit();
            cp_wait<1>();
        } else {
            cp_wait<0>();
        }
        __syncthreads();

        const float* Kc = smf + cur * KBUF;
        const float* Vc = smf + 2*KBUF + cur * VBUF;

        // S = (Q*scale) @ K^T
        float sacc[8][4];
        #pragma unroll
        for (int n = 0; n < 8; n++) {
            sacc[n][0] = sacc[n][1] = sacc[n][2] = sacc[n][3] = 0.f;
            const float* kbase = Kc + (((n << 3) + g) * KSTR) + t;
            #pragma unroll
            for (int k = 0; k < 8; k++) {
                uint32_t b0 = __float_as_uint(kbase[(k << 3)]);
                uint32_t b1 = __float_as_uint(kbase[(k << 3) + 4]);
                mma_tf32(sacc[n], qf[k], b0, b1);
            }
        }

        // Online softmax
        float mx0 = -1e30f, mx1 = -1e30f;
        #pragma unroll
        for (int n = 0; n < 8; n++) {
            mx0 = fmaxf(mx0, fmaxf(sacc[n][0], sacc[n][1]));
            mx1 = fmaxf(mx1, fmaxf(sacc[n][2], sacc[n][3]));
        }
        mx0 = fmaxf(mx0, __shfl_xor_sync(0xffffffffu, mx0, 1));
        mx0 = fmaxf(mx0, __shfl_xor_sync(0xffffffffu, mx0, 2));
        mx1 = fmaxf(mx1, __shfl_xor_sync(0xffffffffu, mx1, 1));
        mx1 = fmaxf(mx1, __shfl_xor_sync(0xffffffffu, mx1, 2));

        float mn0 = fmaxf(m0, mx0);
        float mn1 = fmaxf(m1, mx1);
        float al0 = __expf(m0 - mn0);
        float al1 = __expf(m1 - mn1);
        m0 = mn0; m1 = mn1;

        float rs0 = 0.f, rs1 = 0.f;
        #pragma unroll
        for (int n = 0; n < 8; n++) {
            sacc[n][0] = __expf(sacc[n][0] - mn0);
            sacc[n][1] = __expf(sacc[n][1] - mn0);
            sacc[n][2] = __expf(sacc[n][2] - mn1);
            sacc[n][3] = __expf(sacc[n][3] - mn1);
            rs0 += sacc[n][0] + sacc[n][1];
            rs1 += sacc[n][2] + sacc[n][3];
        }
        rs0 += __shfl_xor_sync(0xffffffffu, rs0, 1);
        rs0 += __shfl_xor_sync(0xffffffffu, rs0, 2);
        rs1 += __shfl_xor_sync(0xffffffffu, rs1, 1);
        rs1 += __shfl_xor_sync(0xffffffffu, rs1, 2);
        l0 = l0 * al0 + rs0;
        l1 = l1 * al1 + rs1;

        #pragma unroll
        for (int n = 0; n < 8; n++) {
            o[n][0] *= al0; o[n][1] *= al0;
            o[n][2] *= al1; o[n][3] *= al1;
        }

        // Stage P (RNA-rounded) through the warp-private Ps slice
        #pragma unroll
        for (int n = 0; n < 8; n++) {
            float2 p01, p23;
            p01.x = tf32rf(sacc[n][0]);
            p01.y = tf32rf(sacc[n][1]);
            p23.x = tf32rf(sacc[n][2]);
            p23.y = tf32rf(sacc[n][3]);
            *(float2*)&Pw[g       * KSTR + (n << 3) + (t << 1)] = p01;
            *(float2*)&Pw[(g + 8) * KSTR + (n << 3) + (t << 1)] = p23;
        }
        __syncwarp();

        uint32_t pf[8][4];
        #pragma unroll
        for (int k = 0; k < 8; k++) {
            pf[k][0] = __float_as_uint(Pw[g       * KSTR + (k << 3) + t]);
            pf[k][1] = __float_as_uint(Pw[(g + 8) * KSTR + (k << 3) + t]);
            pf[k][2] = __float_as_uint(Pw[g       * KSTR + (k << 3) + t + 4]);
            pf[k][3] = __float_as_uint(Pw[(g + 8) * KSTR + (k << 3) + t + 4]);
        }

        // O += P @ V
        #pragma unroll
        for (int n = 0; n < 8; n++) {
            const float* vbase = Vc + t * VSTR + (n << 3) + g;
            #pragma unroll
            for (int k = 0; k < 8; k++) {
                uint32_t b0 = __float_as_uint(vbase[(k << 3) * VSTR]);
                uint32_t b1 = __float_as_uint(vbase[((k << 3) + 4) * VSTR]);
                mma_tf32(o[n], pf[k], b0, b1);
            }
        }
        __syncthreads();   // all reads of cur done before it is re-staged
        cur ^= 1;
    }

    // Epilogue: normalize, tf32-round, write ctx [b,s,d]
    const int b  = bh / H_;
    const int h  = bh - b * H_;
    const float inv0 = 1.0f / l0;
    const float inv1 = 1.0f / l1;
    const int sg0 = q0 + (warp << 4) + g;
    const int sg1 = sg0 + 8;
    float* ctx0 = g_ctx + (size_t)(b * S_ + sg0) * D_ + h * HD_;
    float* ctx1 = g_ctx + (size_t)(b * S_ + sg1) * D_ + h * HD_;
    #pragma unroll
    for (int n = 0; n < 8; n++) {
        float2 r0, r1;
        r0.x = tf32rf(o[n][0] * inv0); r0.y = tf32rf(o[n][1] * inv0);
        r1.x = tf32rf(o[n][2] * inv1); r1.y = tf32rf(o[n][3] * inv1);
        *(float2*)&ctx0[(n << 3) + (t << 1)] = r0;
        *(float2*)&ctx1[(n << 3) + (t << 1)] = r1;
    }
}

// ---------------------------------------------------------------------------
// Launch
// ---------------------------------------------------------------------------
extern "C" void kernel_launch(void* const* d_in, const int* in_sizes, int n_in,
                              void* d_out, int out_size)
{
    (void)in_sizes; (void)n_in; (void)out_size;
    const float* x  = (const float*)d_in[0];
    const float* Wq = (const float*)d_in[1];
    const float* bq = (const float*)d_in[2];
    const float* Wk = (const float*)d_in[3];
    const float* bk = (const float*)d_in[4];
    const float* Wv = (const float*)d_in[5];
    const float* bv = (const float*)d_in[6];
    const float* Wo = (const float*)d_in[7];
    const float* bo = (const float*)d_in[8];
    float* out = (float*)d_out;

    cudaFuncSetAttribute(attn_mma_kernel,
                         cudaFuncAttributeMaxDynamicSharedMemorySize, ATT_SMEM);

    round_all_kernel<<<(N4_TOTAL + 255) / 256, 256>>>(
        (const float4*)x, (const float4*)Wq, (const float4*)Wk,
        (const float4*)Wv, (const float4*)Wo);
    qkv_gemm_kernel<<<dim3(D_/BN, M_/BM, 3), 256>>>(bq, bk, bv);
    attn_mma_kernel<<<dim3(S_/128, B_*H_), 256, ATT_SMEM>>>();
    out_gemm_kernel<<<dim3(D_/BN, M_/BM), 256>>>(bo, out);
}